// round 12
// baseline (speedup 1.0000x reference)
#include <cuda_runtime.h>
#include <cuda.h>
#include <cuda_fp16.h>
#include <math.h>
#include <stdint.h>

// Problem constants
#define T_DIM 8192
#define H_DIM 2048
#define D_DIM 1024

#define KROW_BYTES (D_DIM * 2)        // 2048

#define CHUNK 128
#define NCHUNK (T_DIM / CHUNK)   // 64

// Scratch (allocation-free: __device__ globals)
__device__ __half  g_uh[(size_t)T_DIM * H_DIM];       // 32 MB (u in fp16)
__device__ __half  g_Axh[(size_t)T_DIM * D_DIM];      // 16 MB
__device__ __half  g_Bh[(size_t)H_DIM * D_DIM];       // 4 MB
__device__ float   g_carry[NCHUNK * H_DIM];
__device__ float   g_init[NCHUNK * H_DIM];

// ---------------------------------------------------------------------------
// helpers
// ---------------------------------------------------------------------------
__device__ __forceinline__ uint32_t smem_u32(const void* p) {
    uint32_t a;
    asm("{ .reg .u64 t; cvta.to.shared.u64 t, %1; cvt.u32.u64 %0, t; }" : "=r"(a) : "l"(p));
    return a;
}
__device__ __forceinline__ uint32_t swz128(uint32_t off) { return off ^ ((off >> 3) & 0x70); }

#define MBAR_INIT(addr, cnt) \
    asm volatile("mbarrier.init.shared.b64 [%0], %1;" :: "r"(addr), "r"(cnt) : "memory")
#define MBAR_EXPECT_TX(addr, bytes) \
    asm volatile("mbarrier.arrive.expect_tx.shared.b64 _, [%0], %1;" :: "r"(addr), "r"(bytes) : "memory")

__device__ __forceinline__ void mbar_wait(uint32_t mbar, uint32_t parity) {
    uint32_t done;
    asm volatile(
        "{\n\t.reg .pred p;\n\t"
        "mbarrier.try_wait.parity.acquire.cta.shared::cta.b64 p, [%1], %2;\n\t"
        "selp.b32 %0, 1, 0, p;\n\t}"
        : "=r"(done) : "r"(mbar), "r"(parity) : "memory");
    if (!done) {
        asm volatile(
            "{\n\t.reg .pred P1;\n\t"
            "W_%=:\n\t"
            "mbarrier.try_wait.parity.acquire.cta.shared::cta.b64 P1, [%0], %1, 0x989680;\n\t"
            "@P1 bra.uni D_%=;\n\t"
            "bra.uni W_%=;\n\t"
            "D_%=:\n\t}"
            :: "r"(mbar), "r"(parity) : "memory");
    }
}

#define TMA_LOAD_2D(dst, tmap, cx, cy, mbar) \
    asm volatile("cp.async.bulk.tensor.2d.shared::cluster.global.tile.mbarrier::complete_tx::bytes " \
                 "[%0], [%1, {%2, %3}], [%4];" \
                 :: "r"(dst), "l"(tmap), "r"(cx), "r"(cy), "r"(mbar) : "memory")

#define LDSM_X4(r, addr) \
    asm volatile("ldmatrix.sync.aligned.m8n8.x4.shared.b16 {%0,%1,%2,%3}, [%4];" \
                 : "=r"((r)[0]), "=r"((r)[1]), "=r"((r)[2]), "=r"((r)[3]) : "r"(addr))

#define MMA_F16(c, a, b0, b1) \
    asm volatile("mma.sync.aligned.m16n8k16.row.col.f32.f16.f16.f32 " \
                 "{%0,%1,%2,%3}, {%4,%5,%6,%7}, {%8,%9}, {%0,%1,%2,%3};" \
                 : "+f"((c)[0]), "+f"((c)[1]), "+f"((c)[2]), "+f"((c)[3]) \
                 : "r"((a)[0]), "r"((a)[1]), "r"((a)[2]), "r"((a)[3]), "r"(b0), "r"(b1))

// ---------------------------------------------------------------------------
// Conversions: fp32 -> fp16
// ---------------------------------------------------------------------------
__global__ __launch_bounds__(256)
void convert_x_kernel(const float* __restrict__ x) {
    size_t i4 = (size_t)blockIdx.x * blockDim.x + threadIdx.x;
    size_t base = i4 * 4;
    float4 v = *reinterpret_cast<const float4*>(&x[base]);
    __half2 a = __halves2half2(__float2half_rn(v.x), __float2half_rn(v.y));
    __half2 b = __halves2half2(__float2half_rn(v.z), __float2half_rn(v.w));
    __half2* p = reinterpret_cast<__half2*>(&g_Axh[base]);
    p[0] = a; p[1] = b;
}

__global__ __launch_bounds__(256)
void convert_B_kernel(const float* __restrict__ Bm) {
    size_t i4 = (size_t)blockIdx.x * blockDim.x + threadIdx.x;
    size_t base = i4 * 4;
    float4 v = *reinterpret_cast<const float4*>(&Bm[base]);
    __half2 a = __halves2half2(__float2half_rn(v.x), __float2half_rn(v.y));
    __half2 b = __halves2half2(__float2half_rn(v.z), __float2half_rn(v.w));
    __half2* p = reinterpret_cast<__half2*>(&g_Bh[base]);
    p[0] = a; p[1] = b;
}

// ---------------------------------------------------------------------------
// fp16 mma.sync GEMM: u = x_f16 * B_f16  (fp32 accumulate, fp16 u output)
// Block tile 128x128, 256 threads (2x4 warps), warp tile 64x32.
// 3-stage TMA pipeline, 2 CTAs/SM. Epilogue writes fp16 u and fuses the
// 128-row chunk-carry on the SAME rounded values apply will read.
// ---------------------------------------------------------------------------
#define BM 128
#define BN 128
#define A_SUB 16384
#define B_SUB 16384
#define STAGE_BYTES (A_SUB + B_SUB)        // 32 KB
#define NPIPE 3
#define SMEM_BUFS 1024
#define SMEM_TOTAL (SMEM_BUFS + NPIPE * STAGE_BYTES)  // 99328
#define KSTAGES (D_DIM / 64)               // 16
#define CPAD 132

__global__ __launch_bounds__(256, 2)
void gemm_mma_kernel(const __grid_constant__ CUtensorMap tma_a,
                     const __grid_constant__ CUtensorMap tma_b,
                     const float* __restrict__ lamda) {
    extern __shared__ __align__(1024) char smem[];
    const uint32_t sb = smem_u32(smem);
    const int tid = threadIdx.x;
    const int wid = tid >> 5, lane = tid & 31;
    const int warp_m = wid >> 2;
    const int warp_n = wid & 3;

    const int h0 = blockIdx.x * BN;
    const int t0 = blockIdx.y * BM;       // == chunk * CHUNK

    if (tid == 0) {
#pragma unroll
        for (int i = 0; i < NPIPE; ++i) MBAR_INIT(sb + i * 8, 1);
    }
    __syncthreads();

    auto issue_stage = [&](int s) {
        const int slot = s % NPIPE;
        const uint32_t mbar = sb + slot * 8;
        const uint32_t buf = sb + SMEM_BUFS + slot * STAGE_BYTES;
        MBAR_EXPECT_TX(mbar, STAGE_BYTES);
        TMA_LOAD_2D(buf,         &tma_a, s * 128, t0, mbar);
        TMA_LOAD_2D(buf + A_SUB, &tma_b, s * 128, h0, mbar);
    };

    float acc[4][4][4];
#pragma unroll
    for (int i = 0; i < 4; ++i)
#pragma unroll
        for (int j = 0; j < 4; ++j)
#pragma unroll
            for (int q = 0; q < 4; ++q) acc[i][j][q] = 0.0f;

    if (tid == 0) { issue_stage(0); issue_stage(1); issue_stage(2); }

    for (int s = 0; s < KSTAGES; ++s) {
        mbar_wait(sb + (s % NPIPE) * 8, (uint32_t)((s / NPIPE) & 1));

        const uint32_t ab = sb + SMEM_BUFS + (s % NPIPE) * STAGE_BYTES;
        const uint32_t bb = ab + A_SUB;
        const uint32_t co = (uint32_t)(lane >> 4) * 16;

#pragma unroll
        for (int g = 0; g < 4; ++g) {
            const uint32_t kbase = g * 32;

            uint32_t b_f[2][4];
#pragma unroll
            for (int bt = 0; bt < 2; ++bt) {
                int row = warp_n * 32 + bt * 16 + (lane & 15);
                LDSM_X4(b_f[bt], bb + swz128((uint32_t)(row * 128) + kbase + co));
            }
#pragma unroll
            for (int mt = 0; mt < 4; ++mt) {
                uint32_t a_f[4];
                int row = warp_m * 64 + mt * 16 + (lane & 15);
                LDSM_X4(a_f, ab + swz128((uint32_t)(row * 128) + kbase + co));
#pragma unroll
                for (int nt = 0; nt < 4; ++nt) {
                    const int bt = nt >> 1, hp = nt & 1;
                    MMA_F16(acc[mt][nt], a_f, b_f[bt][hp], b_f[bt][2 + hp]);
                }
            }
        }

        __syncthreads();
        if (tid == 0 && s + 3 < KSTAGES) issue_stage(s + 3);
    }

    // ------- Epilogue: fp16 u write + fused carry on rounded values ---------
    const int r = lane >> 2, c = (lane & 3) * 2;
    __half* Cb = g_uh + (size_t)(t0 + warp_m * 64) * H_DIM + h0 + warp_n * 32;
    float* sf = reinterpret_cast<float*>(smem + SMEM_BUFS);   // [128][CPAD]

#pragma unroll
    for (int mt = 0; mt < 4; ++mt) {
#pragma unroll
        for (int nt = 0; nt < 4; ++nt) {
            __half2 w0 = __floats2half2_rn(acc[mt][nt][0], acc[mt][nt][1]);
            __half2 w1 = __floats2half2_rn(acc[mt][nt][2], acc[mt][nt][3]);
            const int tl0 = warp_m * 64 + mt * 16 + r;
            const int hl  = warp_n * 32 + nt * 8 + c;
            *reinterpret_cast<__half2*>(&Cb[(size_t)(mt * 16 + r) * H_DIM + nt * 8 + c]) = w0;
            *reinterpret_cast<__half2*>(&Cb[(size_t)(mt * 16 + r + 8) * H_DIM + nt * 8 + c]) = w1;
            float2 f0 = __half22float2(w0);
            float2 f1 = __half22float2(w1);
            *reinterpret_cast<float2*>(&sf[tl0 * CPAD + hl]) = f0;
            *reinterpret_cast<float2*>(&sf[(tl0 + 8) * CPAD + hl]) = f1;
        }
    }
    __syncthreads();

    if (tid < BN) {
        const float a = 1.0f / (1.0f + expf(-lamda[h0 + tid]));
        float sc = 0.0f;
#pragma unroll 8
        for (int t = 0; t < CHUNK; ++t) sc = fmaf(a, sc, sf[t * CPAD + tid]);
        g_carry[blockIdx.y * H_DIM + h0 + tid] = sc;
    }
}

// ---------------------------------------------------------------------------
// Scan pass 2: prefetch all 64 carries (MLP), then register chain.
// ---------------------------------------------------------------------------
__global__ __launch_bounds__(256)
void combine_kernel(const float* __restrict__ lamda) {
    const int h = blockIdx.x * blockDim.x + threadIdx.x;
    const float a = 1.0f / (1.0f + expf(-lamda[h]));
    float aC = a;
#pragma unroll
    for (int i = 0; i < 7; ++i) aC *= aC;  // a^128

    float car[NCHUNK];
#pragma unroll
    for (int c = 0; c < NCHUNK; ++c) car[c] = g_carry[c * H_DIM + h];

    float state = 0.0f;
#pragma unroll
    for (int c = 0; c < NCHUNK; ++c) {
        g_init[c * H_DIM + h] = state;
        state = fmaf(aC, state, car[c]);
    }
}

// ---------------------------------------------------------------------------
// Scan pass 3: reads fp16 u, writes fp32 out.
// ---------------------------------------------------------------------------
__global__ __launch_bounds__(256)
void apply_kernel(const float* __restrict__ lamda, float* __restrict__ out) {
    const int h4 = (blockIdx.x * blockDim.x + threadIdx.x) * 4;
    const int c = blockIdx.y;
    float4 lam = *reinterpret_cast<const float4*>(&lamda[h4]);
    float4 a;
    a.x = 1.0f / (1.0f + expf(-lam.x));
    a.y = 1.0f / (1.0f + expf(-lam.y));
    a.z = 1.0f / (1.0f + expf(-lam.z));
    a.w = 1.0f / (1.0f + expf(-lam.w));
    float4 s = *reinterpret_cast<const float4*>(&g_init[c * H_DIM + h4]);
    const size_t base = (size_t)c * CHUNK * H_DIM + h4;
#pragma unroll 4
    for (int t = 0; t < CHUNK; ++t) {
        float2 hv = *reinterpret_cast<const float2*>(&g_uh[base + (size_t)t * H_DIM]);
        __half2 u01 = *reinterpret_cast<__half2*>(&hv.x);
        __half2 u23 = *reinterpret_cast<__half2*>(&hv.y);
        float2 f01 = __half22float2(u01);
        float2 f23 = __half22float2(u23);
        s.x = fmaf(a.x, s.x, f01.x);
        s.y = fmaf(a.y, s.y, f01.y);
        s.z = fmaf(a.z, s.z, f23.x);
        s.w = fmaf(a.w, s.w, f23.y);
        *reinterpret_cast<float4*>(&out[base + (size_t)t * H_DIM]) = s;
    }
}

// ---------------------------------------------------------------------------
// Host: TMA descriptor creation via runtime entry point
// ---------------------------------------------------------------------------
typedef CUresult (*PFN_tmapEncode)(
    CUtensorMap*, CUtensorMapDataType, cuuint32_t, void*,
    const cuuint64_t*, const cuuint64_t*, const cuuint32_t*, const cuuint32_t*,
    CUtensorMapInterleave, CUtensorMapSwizzle, CUtensorMapL2promotion,
    CUtensorMapFloatOOBfill);

extern "C" void kernel_launch(void* const* d_in, const int* in_sizes, int n_in,
                              void* d_out, int out_size) {
    const float* x     = (const float*)d_in[0];  // [T, D]
    const float* lamda = (const float*)d_in[1];  // [H]
    const float* Bm    = (const float*)d_in[2];  // [H, D]
    float* out = (float*)d_out;                  // [T, H]

    void* pfn = nullptr;
    cudaDriverEntryPointQueryResult qres;
    cudaGetDriverEntryPoint("cuTensorMapEncodeTiled", &pfn, cudaEnableDefault, &qres);
    PFN_tmapEncode encode = (PFN_tmapEncode)pfn;

    void *ax_ptr = nullptr, *bx_ptr = nullptr;
    cudaGetSymbolAddress(&ax_ptr, g_Axh);
    cudaGetSymbolAddress(&bx_ptr, g_Bh);

    CUtensorMap tma_a, tma_b;
    {
        cuuint64_t dims[2]    = {KROW_BYTES, T_DIM};
        cuuint64_t strides[1] = {KROW_BYTES};
        cuuint32_t box[2]     = {128, BM};
        cuuint32_t es[2]      = {1, 1};
        encode(&tma_a, CU_TENSOR_MAP_DATA_TYPE_UINT8, 2, ax_ptr,
               dims, strides, box, es,
               CU_TENSOR_MAP_INTERLEAVE_NONE, CU_TENSOR_MAP_SWIZZLE_128B,
               CU_TENSOR_MAP_L2_PROMOTION_L2_128B, CU_TENSOR_MAP_FLOAT_OOB_FILL_NONE);
    }
    {
        cuuint64_t dims[2]    = {KROW_BYTES, H_DIM};
        cuuint64_t strides[1] = {KROW_BYTES};
        cuuint32_t box[2]     = {128, BN};
        cuuint32_t es[2]      = {1, 1};
        encode(&tma_b, CU_TENSOR_MAP_DATA_TYPE_UINT8, 2, bx_ptr,
               dims, strides, box, es,
               CU_TENSOR_MAP_INTERLEAVE_NONE, CU_TENSOR_MAP_SWIZZLE_128B,
               CU_TENSOR_MAP_L2_PROMOTION_L2_128B, CU_TENSOR_MAP_FLOAT_OOB_FILL_NONE);
    }

    convert_x_kernel<<<(T_DIM * D_DIM / 4) / 256, 256>>>(x);
    convert_B_kernel<<<(H_DIM * D_DIM / 4) / 256, 256>>>(Bm);

    cudaFuncSetAttribute(gemm_mma_kernel, cudaFuncAttributeMaxDynamicSharedMemorySize, SMEM_TOTAL);
    dim3 ggrid(H_DIM / BN, T_DIM / BM);   // (16, 64)
    gemm_mma_kernel<<<ggrid, 256, SMEM_TOTAL>>>(tma_a, tma_b, lamda);

    combine_kernel<<<H_DIM / 256, 256>>>(lamda);
    dim3 agrid(H_DIM / 4 / 256, NCHUNK);  // (2, 64)
    apply_kernel<<<agrid, 256>>>(lamda, out);
}

// round 13
// speedup vs baseline: 1.1290x; 1.1290x over previous
#include <cuda_runtime.h>
#include <cuda.h>
#include <cuda_fp16.h>
#include <math.h>
#include <stdint.h>

// Problem constants
#define T_DIM 8192
#define H_DIM 2048
#define D_DIM 1024

#define KROW_BYTES (D_DIM * 2)        // 2048

#define CHUNK 128
#define NCHUNK (T_DIM / CHUNK)   // 64

// Scratch (allocation-free: __device__ globals)
__device__ float   g_u[(size_t)T_DIM * H_DIM];        // 64 MB
__device__ __half  g_Axh[(size_t)T_DIM * D_DIM];      // 16 MB
__device__ __half  g_Bh[(size_t)H_DIM * D_DIM];       // 4 MB
__device__ float   g_carry[NCHUNK * H_DIM];
__device__ float   g_init[NCHUNK * H_DIM];

// ---------------------------------------------------------------------------
// helpers
// ---------------------------------------------------------------------------
__device__ __forceinline__ uint32_t smem_u32(const void* p) {
    uint32_t a;
    asm("{ .reg .u64 t; cvta.to.shared.u64 t, %1; cvt.u32.u64 %0, t; }" : "=r"(a) : "l"(p));
    return a;
}
__device__ __forceinline__ uint32_t swz128(uint32_t off) { return off ^ ((off >> 3) & 0x70); }

#define MBAR_INIT(addr, cnt) \
    asm volatile("mbarrier.init.shared.b64 [%0], %1;" :: "r"(addr), "r"(cnt) : "memory")
#define MBAR_EXPECT_TX(addr, bytes) \
    asm volatile("mbarrier.arrive.expect_tx.shared.b64 _, [%0], %1;" :: "r"(addr), "r"(bytes) : "memory")

__device__ __forceinline__ void mbar_wait(uint32_t mbar, uint32_t parity) {
    uint32_t done;
    asm volatile(
        "{\n\t.reg .pred p;\n\t"
        "mbarrier.try_wait.parity.acquire.cta.shared::cta.b64 p, [%1], %2;\n\t"
        "selp.b32 %0, 1, 0, p;\n\t}"
        : "=r"(done) : "r"(mbar), "r"(parity) : "memory");
    if (!done) {
        asm volatile(
            "{\n\t.reg .pred P1;\n\t"
            "W_%=:\n\t"
            "mbarrier.try_wait.parity.acquire.cta.shared::cta.b64 P1, [%0], %1, 0x989680;\n\t"
            "@P1 bra.uni D_%=;\n\t"
            "bra.uni W_%=;\n\t"
            "D_%=:\n\t}"
            :: "r"(mbar), "r"(parity) : "memory");
    }
}

#define TMA_LOAD_2D(dst, tmap, cx, cy, mbar) \
    asm volatile("cp.async.bulk.tensor.2d.shared::cluster.global.tile.mbarrier::complete_tx::bytes " \
                 "[%0], [%1, {%2, %3}], [%4];" \
                 :: "r"(dst), "l"(tmap), "r"(cx), "r"(cy), "r"(mbar) : "memory")

#define LDSM_X4(r, addr) \
    asm volatile("ldmatrix.sync.aligned.m8n8.x4.shared.b16 {%0,%1,%2,%3}, [%4];" \
                 : "=r"((r)[0]), "=r"((r)[1]), "=r"((r)[2]), "=r"((r)[3]) : "r"(addr))

#define MMA_F16(c, a, b0, b1) \
    asm volatile("mma.sync.aligned.m16n8k16.row.col.f32.f16.f16.f32 " \
                 "{%0,%1,%2,%3}, {%4,%5,%6,%7}, {%8,%9}, {%0,%1,%2,%3};" \
                 : "+f"((c)[0]), "+f"((c)[1]), "+f"((c)[2]), "+f"((c)[3]) \
                 : "r"((a)[0]), "r"((a)[1]), "r"((a)[2]), "r"((a)[3]), "r"(b0), "r"(b1))

// ---------------------------------------------------------------------------
// Conversion: fp32 -> fp16, x and B merged into one launch.
// Blocks [0, NXB) handle x; blocks [NXB, NXB+NBB) handle B.
// ---------------------------------------------------------------------------
#define NXB ((T_DIM * D_DIM / 4) / 256)   // 8192
#define NBB ((H_DIM * D_DIM / 4) / 256)   // 2048

__global__ __launch_bounds__(256)
void convert_kernel(const float* __restrict__ x, const float* __restrict__ Bm) {
    int b = blockIdx.x;
    const float* src;
    __half* dst;
    size_t i4;
    if (b < NXB) {
        src = x;  dst = g_Axh;
        i4 = (size_t)b * 256 + threadIdx.x;
    } else {
        src = Bm; dst = g_Bh;
        i4 = (size_t)(b - NXB) * 256 + threadIdx.x;
    }
    size_t base = i4 * 4;
    float4 v = *reinterpret_cast<const float4*>(&src[base]);
    __half2 a = __halves2half2(__float2half_rn(v.x), __float2half_rn(v.y));
    __half2 c = __halves2half2(__float2half_rn(v.z), __float2half_rn(v.w));
    __half2* p = reinterpret_cast<__half2*>(&dst[base]);
    p[0] = a; p[1] = c;
}

// ---------------------------------------------------------------------------
// fp16 mma.sync GEMM: u = x_f16 * B_f16  (fp32 accumulate)
// Block tile 128x128, 256 threads (2x4 warps), warp tile 64x32.
// 3-stage TMA pipeline, 2 CTAs/SM. All LDSM of a k16 step hoisted ahead of
// its 16 MMAs (asm volatile preserves order; avoids per-mt scoreboard stalls).
// Epilogue fuses 128-row chunk-carry computation.
// ---------------------------------------------------------------------------
#define BM 128
#define BN 128
#define A_SUB 16384
#define B_SUB 16384
#define STAGE_BYTES (A_SUB + B_SUB)        // 32 KB
#define NPIPE 3
#define SMEM_BUFS 1024
#define SMEM_TOTAL (SMEM_BUFS + NPIPE * STAGE_BYTES)  // 99328
#define KSTAGES (D_DIM / 64)               // 16
#define CPAD 132

__global__ __launch_bounds__(256, 2)
void gemm_mma_kernel(const __grid_constant__ CUtensorMap tma_a,
                     const __grid_constant__ CUtensorMap tma_b,
                     const float* __restrict__ lamda) {
    extern __shared__ __align__(1024) char smem[];
    const uint32_t sb = smem_u32(smem);
    const int tid = threadIdx.x;
    const int wid = tid >> 5, lane = tid & 31;
    const int warp_m = wid >> 2;          // 0..1  (64 t-rows each)
    const int warp_n = wid & 3;           // 0..3  (32 h-cols each)

    const int h0 = blockIdx.x * BN;
    const int t0 = blockIdx.y * BM;       // == chunk * CHUNK

    if (tid == 0) {
#pragma unroll
        for (int i = 0; i < NPIPE; ++i) MBAR_INIT(sb + i * 8, 1);
    }
    __syncthreads();

    auto issue_stage = [&](int s) {
        const int slot = s % NPIPE;
        const uint32_t mbar = sb + slot * 8;
        const uint32_t buf = sb + SMEM_BUFS + slot * STAGE_BYTES;
        MBAR_EXPECT_TX(mbar, STAGE_BYTES);
        TMA_LOAD_2D(buf,         &tma_a, s * 128, t0, mbar);
        TMA_LOAD_2D(buf + A_SUB, &tma_b, s * 128, h0, mbar);
    };

    float acc[4][4][4];
#pragma unroll
    for (int i = 0; i < 4; ++i)
#pragma unroll
        for (int j = 0; j < 4; ++j)
#pragma unroll
            for (int q = 0; q < 4; ++q) acc[i][j][q] = 0.0f;

    if (tid == 0) { issue_stage(0); issue_stage(1); issue_stage(2); }

    for (int s = 0; s < KSTAGES; ++s) {
        mbar_wait(sb + (s % NPIPE) * 8, (uint32_t)((s / NPIPE) & 1));

        const uint32_t ab = sb + SMEM_BUFS + (s % NPIPE) * STAGE_BYTES;
        const uint32_t bb = ab + A_SUB;
        const uint32_t co = (uint32_t)(lane >> 4) * 16;

#pragma unroll
        for (int g = 0; g < 4; ++g) {            // four k16 steps per stage
            const uint32_t kbase = g * 32;

            // ---- hoist ALL fragment loads for this k16 step ----
            uint32_t b_f[2][4], a_f[4][4];
#pragma unroll
            for (int bt = 0; bt < 2; ++bt) {
                int row = warp_n * 32 + bt * 16 + (lane & 15);
                LDSM_X4(b_f[bt], bb + swz128((uint32_t)(row * 128) + kbase + co));
            }
#pragma unroll
            for (int mt = 0; mt < 4; ++mt) {
                int row = warp_m * 64 + mt * 16 + (lane & 15);
                LDSM_X4(a_f[mt], ab + swz128((uint32_t)(row * 128) + kbase + co));
            }
            // ---- 16 independent-acc MMAs, no interleaved loads ----
#pragma unroll
            for (int mt = 0; mt < 4; ++mt)
#pragma unroll
                for (int nt = 0; nt < 4; ++nt) {
                    const int bt = nt >> 1, hp = nt & 1;
                    MMA_F16(acc[mt][nt], a_f[mt], b_f[bt][hp], b_f[bt][2 + hp]);
                }
        }

        __syncthreads();                 // all warps done with this slot
        if (tid == 0 && s + 3 < KSTAGES) issue_stage(s + 3);
    }

    // ---------------- Epilogue: write g_u + fused 128-row chunk-carry ---------
    const int r = lane >> 2, c = (lane & 3) * 2;
    float* Cb = g_u + (size_t)(t0 + warp_m * 64) * H_DIM + h0 + warp_n * 32;
    float* sf = reinterpret_cast<float*>(smem + SMEM_BUFS);   // [128][CPAD] staging

#pragma unroll
    for (int mt = 0; mt < 4; ++mt) {
#pragma unroll
        for (int nt = 0; nt < 4; ++nt) {
            float2 v0 = make_float2(acc[mt][nt][0], acc[mt][nt][1]);
            float2 v1 = make_float2(acc[mt][nt][2], acc[mt][nt][3]);
            const int tl0 = warp_m * 64 + mt * 16 + r;
            const int hl  = warp_n * 32 + nt * 8 + c;
            *reinterpret_cast<float2*>(&Cb[(size_t)(mt * 16 + r) * H_DIM + nt * 8 + c]) = v0;
            *reinterpret_cast<float2*>(&Cb[(size_t)(mt * 16 + r + 8) * H_DIM + nt * 8 + c]) = v1;
            *reinterpret_cast<float2*>(&sf[tl0 * CPAD + hl]) = v0;
            *reinterpret_cast<float2*>(&sf[(tl0 + 8) * CPAD + hl]) = v1;
        }
    }
    __syncthreads();

    if (tid < BN) {
        const float a = 1.0f / (1.0f + expf(-lamda[h0 + tid]));
        float sc = 0.0f;
#pragma unroll 8
        for (int t = 0; t < CHUNK; ++t) sc = fmaf(a, sc, sf[t * CPAD + tid]);
        g_carry[blockIdx.y * H_DIM + h0 + tid] = sc;
    }
}

// ---------------------------------------------------------------------------
// Scan pass 2: prefetch all 64 carries (MLP), then register chain.
// ---------------------------------------------------------------------------
__global__ __launch_bounds__(256)
void combine_kernel(const float* __restrict__ lamda) {
    const int h = blockIdx.x * blockDim.x + threadIdx.x;
    const float a = 1.0f / (1.0f + expf(-lamda[h]));
    float aC = a;
#pragma unroll
    for (int i = 0; i < 7; ++i) aC *= aC;  // a^128

    float car[NCHUNK];
#pragma unroll
    for (int c = 0; c < NCHUNK; ++c) car[c] = g_carry[c * H_DIM + h];

    float state = 0.0f;
#pragma unroll
    for (int c = 0; c < NCHUNK; ++c) {
        g_init[c * H_DIM + h] = state;
        state = fmaf(aC, state, car[c]);
    }
}

// ---------------------------------------------------------------------------
// Scan pass 3: vectorized (float4 over h), exact per-chunk rerun.
// Streaming stores (out is write-once; keep L2 for g_u).
// ---------------------------------------------------------------------------
__global__ __launch_bounds__(256)
void apply_kernel(const float* __restrict__ lamda, float* __restrict__ out) {
    const int h4 = (blockIdx.x * blockDim.x + threadIdx.x) * 4;
    const int c = blockIdx.y;
    float4 lam = *reinterpret_cast<const float4*>(&lamda[h4]);
    float4 a;
    a.x = 1.0f / (1.0f + expf(-lam.x));
    a.y = 1.0f / (1.0f + expf(-lam.y));
    a.z = 1.0f / (1.0f + expf(-lam.z));
    a.w = 1.0f / (1.0f + expf(-lam.w));
    float4 s = *reinterpret_cast<const float4*>(&g_init[c * H_DIM + h4]);
    const size_t base = (size_t)c * CHUNK * H_DIM + h4;
#pragma unroll 4
    for (int t = 0; t < CHUNK; ++t) {
        float4 u = *reinterpret_cast<const float4*>(&g_u[base + (size_t)t * H_DIM]);
        s.x = fmaf(a.x, s.x, u.x);
        s.y = fmaf(a.y, s.y, u.y);
        s.z = fmaf(a.z, s.z, u.z);
        s.w = fmaf(a.w, s.w, u.w);
        __stcs(reinterpret_cast<float4*>(&out[base + (size_t)t * H_DIM]), s);
    }
}

// ---------------------------------------------------------------------------
// Host: TMA descriptor creation via runtime entry point
// ---------------------------------------------------------------------------
typedef CUresult (*PFN_tmapEncode)(
    CUtensorMap*, CUtensorMapDataType, cuuint32_t, void*,
    const cuuint64_t*, const cuuint64_t*, const cuuint32_t*, const cuuint32_t*,
    CUtensorMapInterleave, CUtensorMapSwizzle, CUtensorMapL2promotion,
    CUtensorMapFloatOOBfill);

extern "C" void kernel_launch(void* const* d_in, const int* in_sizes, int n_in,
                              void* d_out, int out_size) {
    const float* x     = (const float*)d_in[0];  // [T, D]
    const float* lamda = (const float*)d_in[1];  // [H]
    const float* Bm    = (const float*)d_in[2];  // [H, D]
    float* out = (float*)d_out;                  // [T, H]

    void* pfn = nullptr;
    cudaDriverEntryPointQueryResult qres;
    cudaGetDriverEntryPoint("cuTensorMapEncodeTiled", &pfn, cudaEnableDefault, &qres);
    PFN_tmapEncode encode = (PFN_tmapEncode)pfn;

    void *ax_ptr = nullptr, *bx_ptr = nullptr;
    cudaGetSymbolAddress(&ax_ptr, g_Axh);
    cudaGetSymbolAddress(&bx_ptr, g_Bh);

    CUtensorMap tma_a, tma_b;
    {
        cuuint64_t dims[2]    = {KROW_BYTES, T_DIM};
        cuuint64_t strides[1] = {KROW_BYTES};
        cuuint32_t box[2]     = {128, BM};
        cuuint32_t es[2]      = {1, 1};
        encode(&tma_a, CU_TENSOR_MAP_DATA_TYPE_UINT8, 2, ax_ptr,
               dims, strides, box, es,
               CU_TENSOR_MAP_INTERLEAVE_NONE, CU_TENSOR_MAP_SWIZZLE_128B,
               CU_TENSOR_MAP_L2_PROMOTION_L2_128B, CU_TENSOR_MAP_FLOAT_OOB_FILL_NONE);
    }
    {
        cuuint64_t dims[2]    = {KROW_BYTES, H_DIM};
        cuuint64_t strides[1] = {KROW_BYTES};
        cuuint32_t box[2]     = {128, BN};
        cuuint32_t es[2]      = {1, 1};
        encode(&tma_b, CU_TENSOR_MAP_DATA_TYPE_UINT8, 2, bx_ptr,
               dims, strides, box, es,
               CU_TENSOR_MAP_INTERLEAVE_NONE, CU_TENSOR_MAP_SWIZZLE_128B,
               CU_TENSOR_MAP_L2_PROMOTION_L2_128B, CU_TENSOR_MAP_FLOAT_OOB_FILL_NONE);
    }

    convert_kernel<<<NXB + NBB, 256>>>(x, Bm);

    cudaFuncSetAttribute(gemm_mma_kernel, cudaFuncAttributeMaxDynamicSharedMemorySize, SMEM_TOTAL);
    dim3 ggrid(H_DIM / BN, T_DIM / BM);   // (16, 64)
    gemm_mma_kernel<<<ggrid, 256, SMEM_TOTAL>>>(tma_a, tma_b, lamda);

    combine_kernel<<<H_DIM / 256, 256>>>(lamda);
    dim3 agrid(H_DIM / 4 / 256, NCHUNK);  // (2, 64)
    apply_kernel<<<agrid, 256>>>(lamda, out);
}

// round 14
// speedup vs baseline: 1.4071x; 1.2463x over previous
#include <cuda_runtime.h>
#include <cuda.h>
#include <cuda_fp16.h>
#include <math.h>
#include <stdint.h>

// Problem constants
#define T_DIM 8192
#define H_DIM 2048
#define D_DIM 1024

#define KROW_BYTES (D_DIM * 2)        // 2048

#define CHUNK 128
#define NCHUNK (T_DIM / CHUNK)   // 64

// Scratch (allocation-free: __device__ globals)
__device__ float   g_u[(size_t)T_DIM * H_DIM];        // 64 MB
__device__ __half  g_Axh[(size_t)T_DIM * D_DIM];      // 16 MB
__device__ __half  g_Bh[(size_t)H_DIM * D_DIM];       // 4 MB
__device__ float   g_carry[NCHUNK * H_DIM];
__device__ float   g_init[NCHUNK * H_DIM];

// ---------------------------------------------------------------------------
// helpers
// ---------------------------------------------------------------------------
__device__ __forceinline__ uint32_t smem_u32(const void* p) {
    uint32_t a;
    asm("{ .reg .u64 t; cvta.to.shared.u64 t, %1; cvt.u32.u64 %0, t; }" : "=r"(a) : "l"(p));
    return a;
}
__device__ __forceinline__ uint32_t swz128(uint32_t off) { return off ^ ((off >> 3) & 0x70); }

#define MBAR_INIT(addr, cnt) \
    asm volatile("mbarrier.init.shared.b64 [%0], %1;" :: "r"(addr), "r"(cnt) : "memory")
#define MBAR_EXPECT_TX(addr, bytes) \
    asm volatile("mbarrier.arrive.expect_tx.shared.b64 _, [%0], %1;" :: "r"(addr), "r"(bytes) : "memory")

__device__ __forceinline__ void mbar_wait(uint32_t mbar, uint32_t parity) {
    uint32_t done;
    asm volatile(
        "{\n\t.reg .pred p;\n\t"
        "mbarrier.try_wait.parity.acquire.cta.shared::cta.b64 p, [%1], %2;\n\t"
        "selp.b32 %0, 1, 0, p;\n\t}"
        : "=r"(done) : "r"(mbar), "r"(parity) : "memory");
    if (!done) {
        asm volatile(
            "{\n\t.reg .pred P1;\n\t"
            "W_%=:\n\t"
            "mbarrier.try_wait.parity.acquire.cta.shared::cta.b64 P1, [%0], %1, 0x989680;\n\t"
            "@P1 bra.uni D_%=;\n\t"
            "bra.uni W_%=;\n\t"
            "D_%=:\n\t}"
            :: "r"(mbar), "r"(parity) : "memory");
    }
}

#define TMA_LOAD_2D(dst, tmap, cx, cy, mbar) \
    asm volatile("cp.async.bulk.tensor.2d.shared::cluster.global.tile.mbarrier::complete_tx::bytes " \
                 "[%0], [%1, {%2, %3}], [%4];" \
                 :: "r"(dst), "l"(tmap), "r"(cx), "r"(cy), "r"(mbar) : "memory")

#define LDSM_X4(r, addr) \
    asm volatile("ldmatrix.sync.aligned.m8n8.x4.shared.b16 {%0,%1,%2,%3}, [%4];" \
                 : "=r"((r)[0]), "=r"((r)[1]), "=r"((r)[2]), "=r"((r)[3]) : "r"(addr))

#define MMA_F16(c, a, b0, b1) \
    asm volatile("mma.sync.aligned.m16n8k16.row.col.f32.f16.f16.f32 " \
                 "{%0,%1,%2,%3}, {%4,%5,%6,%7}, {%8,%9}, {%0,%1,%2,%3};" \
                 : "+f"((c)[0]), "+f"((c)[1]), "+f"((c)[2]), "+f"((c)[3]) \
                 : "r"((a)[0]), "r"((a)[1]), "r"((a)[2]), "r"((a)[3]), "r"(b0), "r"(b1))

// ---------------------------------------------------------------------------
// Conversion: fp32 -> fp16, x and B merged into one launch.
// Blocks [0, NXB) handle x; blocks [NXB, NXB+NBB) handle B.
// ---------------------------------------------------------------------------
#define NXB ((T_DIM * D_DIM / 4) / 256)   // 8192
#define NBB ((H_DIM * D_DIM / 4) / 256)   // 2048

__global__ __launch_bounds__(256)
void convert_kernel(const float* __restrict__ x, const float* __restrict__ Bm) {
    int b = blockIdx.x;
    const float* src;
    __half* dst;
    size_t i4;
    if (b < NXB) {
        src = x;  dst = g_Axh;
        i4 = (size_t)b * 256 + threadIdx.x;
    } else {
        src = Bm; dst = g_Bh;
        i4 = (size_t)(b - NXB) * 256 + threadIdx.x;
    }
    size_t base = i4 * 4;
    float4 v = *reinterpret_cast<const float4*>(&src[base]);
    __half2 a = __halves2half2(__float2half_rn(v.x), __float2half_rn(v.y));
    __half2 c = __halves2half2(__float2half_rn(v.z), __float2half_rn(v.w));
    __half2* p = reinterpret_cast<__half2*>(&dst[base]);
    p[0] = a; p[1] = c;
}

// ---------------------------------------------------------------------------
// fp16 mma.sync GEMM: u = x_f16 * B_f16  (fp32 accumulate)
// Block tile 128x128, 256 threads (2x4 warps), warp tile 64x32.
// 3-stage TMA pipeline, 2 CTAs/SM. All LDSM of a k16 step hoisted ahead of
// its 16 MMAs. Epilogue fuses 128-row chunk-carry computation.
// ---------------------------------------------------------------------------
#define BM 128
#define BN 128
#define A_SUB 16384
#define B_SUB 16384
#define STAGE_BYTES (A_SUB + B_SUB)        // 32 KB
#define NPIPE 3
#define SMEM_BUFS 1024
#define SMEM_TOTAL (SMEM_BUFS + NPIPE * STAGE_BYTES)  // 99328
#define KSTAGES (D_DIM / 64)               // 16
#define CPAD 132

__global__ __launch_bounds__(256, 2)
void gemm_mma_kernel(const __grid_constant__ CUtensorMap tma_a,
                     const __grid_constant__ CUtensorMap tma_b,
                     const float* __restrict__ lamda) {
    extern __shared__ __align__(1024) char smem[];
    const uint32_t sb = smem_u32(smem);
    const int tid = threadIdx.x;
    const int wid = tid >> 5, lane = tid & 31;
    const int warp_m = wid >> 2;          // 0..1  (64 t-rows each)
    const int warp_n = wid & 3;           // 0..3  (32 h-cols each)

    const int h0 = blockIdx.x * BN;
    const int t0 = blockIdx.y * BM;       // == chunk * CHUNK

    if (tid == 0) {
#pragma unroll
        for (int i = 0; i < NPIPE; ++i) MBAR_INIT(sb + i * 8, 1);
    }
    __syncthreads();

    auto issue_stage = [&](int s) {
        const int slot = s % NPIPE;
        const uint32_t mbar = sb + slot * 8;
        const uint32_t buf = sb + SMEM_BUFS + slot * STAGE_BYTES;
        MBAR_EXPECT_TX(mbar, STAGE_BYTES);
        TMA_LOAD_2D(buf,         &tma_a, s * 128, t0, mbar);
        TMA_LOAD_2D(buf + A_SUB, &tma_b, s * 128, h0, mbar);
    };

    float acc[4][4][4];
#pragma unroll
    for (int i = 0; i < 4; ++i)
#pragma unroll
        for (int j = 0; j < 4; ++j)
#pragma unroll
            for (int q = 0; q < 4; ++q) acc[i][j][q] = 0.0f;

    if (tid == 0) { issue_stage(0); issue_stage(1); issue_stage(2); }

    for (int s = 0; s < KSTAGES; ++s) {
        mbar_wait(sb + (s % NPIPE) * 8, (uint32_t)((s / NPIPE) & 1));

        const uint32_t ab = sb + SMEM_BUFS + (s % NPIPE) * STAGE_BYTES;
        const uint32_t bb = ab + A_SUB;
        const uint32_t co = (uint32_t)(lane >> 4) * 16;

#pragma unroll
        for (int g = 0; g < 4; ++g) {            // four k16 steps per stage
            const uint32_t kbase = g * 32;

            // ---- hoist ALL fragment loads for this k16 step ----
            uint32_t b_f[2][4], a_f[4][4];
#pragma unroll
            for (int bt = 0; bt < 2; ++bt) {
                int row = warp_n * 32 + bt * 16 + (lane & 15);
                LDSM_X4(b_f[bt], bb + swz128((uint32_t)(row * 128) + kbase + co));
            }
#pragma unroll
            for (int mt = 0; mt < 4; ++mt) {
                int row = warp_m * 64 + mt * 16 + (lane & 15);
                LDSM_X4(a_f[mt], ab + swz128((uint32_t)(row * 128) + kbase + co));
            }
            // ---- 16 independent-acc MMAs, no interleaved loads ----
#pragma unroll
            for (int mt = 0; mt < 4; ++mt)
#pragma unroll
                for (int nt = 0; nt < 4; ++nt) {
                    const int bt = nt >> 1, hp = nt & 1;
                    MMA_F16(acc[mt][nt], a_f[mt], b_f[bt][hp], b_f[bt][2 + hp]);
                }
        }

        __syncthreads();                 // all warps done with this slot
        if (tid == 0 && s + 3 < KSTAGES) issue_stage(s + 3);
    }

    // ---------------- Epilogue: write g_u + fused 128-row chunk-carry ---------
    const int r = lane >> 2, c = (lane & 3) * 2;
    float* Cb = g_u + (size_t)(t0 + warp_m * 64) * H_DIM + h0 + warp_n * 32;
    float* sf = reinterpret_cast<float*>(smem + SMEM_BUFS);   // [128][CPAD] staging

#pragma unroll
    for (int mt = 0; mt < 4; ++mt) {
#pragma unroll
        for (int nt = 0; nt < 4; ++nt) {
            float2 v0 = make_float2(acc[mt][nt][0], acc[mt][nt][1]);
            float2 v1 = make_float2(acc[mt][nt][2], acc[mt][nt][3]);
            const int tl0 = warp_m * 64 + mt * 16 + r;
            const int hl  = warp_n * 32 + nt * 8 + c;
            *reinterpret_cast<float2*>(&Cb[(size_t)(mt * 16 + r) * H_DIM + nt * 8 + c]) = v0;
            *reinterpret_cast<float2*>(&Cb[(size_t)(mt * 16 + r + 8) * H_DIM + nt * 8 + c]) = v1;
            *reinterpret_cast<float2*>(&sf[tl0 * CPAD + hl]) = v0;
            *reinterpret_cast<float2*>(&sf[(tl0 + 8) * CPAD + hl]) = v1;
        }
    }
    __syncthreads();

    if (tid < BN) {
        const float a = 1.0f / (1.0f + expf(-lamda[h0 + tid]));
        float sc = 0.0f;
#pragma unroll 8
        for (int t = 0; t < CHUNK; ++t) sc = fmaf(a, sc, sf[t * CPAD + tid]);
        g_carry[blockIdx.y * H_DIM + h0 + tid] = sc;
    }
}

// ---------------------------------------------------------------------------
// Scan pass 2: prefetch all 64 carries (MLP), then register chain.
// ---------------------------------------------------------------------------
__global__ __launch_bounds__(256)
void combine_kernel(const float* __restrict__ lamda) {
    const int h = blockIdx.x * blockDim.x + threadIdx.x;
    const float a = 1.0f / (1.0f + expf(-lamda[h]));
    float aC = a;
#pragma unroll
    for (int i = 0; i < 7; ++i) aC *= aC;  // a^128

    float car[NCHUNK];
#pragma unroll
    for (int c = 0; c < NCHUNK; ++c) car[c] = g_carry[c * H_DIM + h];

    float state = 0.0f;
#pragma unroll
    for (int c = 0; c < NCHUNK; ++c) {
        g_init[c * H_DIM + h] = state;
        state = fmaf(aC, state, car[c]);
    }
}

// ---------------------------------------------------------------------------
// Scan pass 3: vectorized (float4 over h), exact per-chunk rerun.
// 128-thread blocks -> 256 CTAs so all 148 SMs are covered. Plain stores.
// ---------------------------------------------------------------------------
__global__ __launch_bounds__(128)
void apply_kernel(const float* __restrict__ lamda, float* __restrict__ out) {
    const int h4 = (blockIdx.x * blockDim.x + threadIdx.x) * 4;
    const int c = blockIdx.y;
    float4 lam = *reinterpret_cast<const float4*>(&lamda[h4]);
    float4 a;
    a.x = 1.0f / (1.0f + expf(-lam.x));
    a.y = 1.0f / (1.0f + expf(-lam.y));
    a.z = 1.0f / (1.0f + expf(-lam.z));
    a.w = 1.0f / (1.0f + expf(-lam.w));
    float4 s = *reinterpret_cast<const float4*>(&g_init[c * H_DIM + h4]);
    const size_t base = (size_t)c * CHUNK * H_DIM + h4;
#pragma unroll 4
    for (int t = 0; t < CHUNK; ++t) {
        float4 u = *reinterpret_cast<const float4*>(&g_u[base + (size_t)t * H_DIM]);
        s.x = fmaf(a.x, s.x, u.x);
        s.y = fmaf(a.y, s.y, u.y);
        s.z = fmaf(a.z, s.z, u.z);
        s.w = fmaf(a.w, s.w, u.w);
        *reinterpret_cast<float4*>(&out[base + (size_t)t * H_DIM]) = s;
    }
}

// ---------------------------------------------------------------------------
// Host: TMA descriptor creation via runtime entry point
// ---------------------------------------------------------------------------
typedef CUresult (*PFN_tmapEncode)(
    CUtensorMap*, CUtensorMapDataType, cuuint32_t, void*,
    const cuuint64_t*, const cuuint64_t*, const cuuint32_t*, const cuuint32_t*,
    CUtensorMapInterleave, CUtensorMapSwizzle, CUtensorMapL2promotion,
    CUtensorMapFloatOOBfill);

extern "C" void kernel_launch(void* const* d_in, const int* in_sizes, int n_in,
                              void* d_out, int out_size) {
    const float* x     = (const float*)d_in[0];  // [T, D]
    const float* lamda = (const float*)d_in[1];  // [H]
    const float* Bm    = (const float*)d_in[2];  // [H, D]
    float* out = (float*)d_out;                  // [T, H]

    void* pfn = nullptr;
    cudaDriverEntryPointQueryResult qres;
    cudaGetDriverEntryPoint("cuTensorMapEncodeTiled", &pfn, cudaEnableDefault, &qres);
    PFN_tmapEncode encode = (PFN_tmapEncode)pfn;

    void *ax_ptr = nullptr, *bx_ptr = nullptr;
    cudaGetSymbolAddress(&ax_ptr, g_Axh);
    cudaGetSymbolAddress(&bx_ptr, g_Bh);

    CUtensorMap tma_a, tma_b;
    {
        cuuint64_t dims[2]    = {KROW_BYTES, T_DIM};
        cuuint64_t strides[1] = {KROW_BYTES};
        cuuint32_t box[2]     = {128, BM};
        cuuint32_t es[2]      = {1, 1};
        encode(&tma_a, CU_TENSOR_MAP_DATA_TYPE_UINT8, 2, ax_ptr,
               dims, strides, box, es,
               CU_TENSOR_MAP_INTERLEAVE_NONE, CU_TENSOR_MAP_SWIZZLE_128B,
               CU_TENSOR_MAP_L2_PROMOTION_L2_128B, CU_TENSOR_MAP_FLOAT_OOB_FILL_NONE);
    }
    {
        cuuint64_t dims[2]    = {KROW_BYTES, H_DIM};
        cuuint64_t strides[1] = {KROW_BYTES};
        cuuint32_t box[2]     = {128, BN};
        cuuint32_t es[2]      = {1, 1};
        encode(&tma_b, CU_TENSOR_MAP_DATA_TYPE_UINT8, 2, bx_ptr,
               dims, strides, box, es,
               CU_TENSOR_MAP_INTERLEAVE_NONE, CU_TENSOR_MAP_SWIZZLE_128B,
               CU_TENSOR_MAP_L2_PROMOTION_L2_128B, CU_TENSOR_MAP_FLOAT_OOB_FILL_NONE);
    }

    convert_kernel<<<NXB + NBB, 256>>>(x, Bm);

    cudaFuncSetAttribute(gemm_mma_kernel, cudaFuncAttributeMaxDynamicSharedMemorySize, SMEM_TOTAL);
    dim3 ggrid(H_DIM / BN, T_DIM / BM);   // (16, 64)
    gemm_mma_kernel<<<ggrid, 256, SMEM_TOTAL>>>(tma_a, tma_b, lamda);

    combine_kernel<<<H_DIM / 256, 256>>>(lamda);
    dim3 agrid(H_DIM / 4 / 128, NCHUNK);  // (4, 64) = 256 CTAs
    apply_kernel<<<agrid, 128>>>(lamda, out);
}

// round 15
// speedup vs baseline: 1.4506x; 1.0309x over previous
#include <cuda_runtime.h>
#include <cuda.h>
#include <cuda_fp16.h>
#include <math.h>
#include <stdint.h>

// Problem constants
#define T_DIM 8192
#define H_DIM 2048
#define D_DIM 1024

#define KROW_BYTES (D_DIM * 2)        // 2048

// GEMM tile chunk is 128 rows; scan sub-chunk is 64 rows (2 per tile).
#define CHUNK2 64
#define NC2 (T_DIM / CHUNK2)          // 128

// Scratch (allocation-free: __device__ globals)
__device__ float   g_u[(size_t)T_DIM * H_DIM];        // 64 MB
__device__ __half  g_Axh[(size_t)T_DIM * D_DIM];      // 16 MB
__device__ __half  g_Bh[(size_t)H_DIM * D_DIM];       // 4 MB
__device__ float   g_carry[NC2 * H_DIM];
__device__ float   g_init[NC2 * H_DIM];

// ---------------------------------------------------------------------------
// helpers
// ---------------------------------------------------------------------------
__device__ __forceinline__ uint32_t smem_u32(const void* p) {
    uint32_t a;
    asm("{ .reg .u64 t; cvta.to.shared.u64 t, %1; cvt.u32.u64 %0, t; }" : "=r"(a) : "l"(p));
    return a;
}
__device__ __forceinline__ uint32_t swz128(uint32_t off) { return off ^ ((off >> 3) & 0x70); }

#define MBAR_INIT(addr, cnt) \
    asm volatile("mbarrier.init.shared.b64 [%0], %1;" :: "r"(addr), "r"(cnt) : "memory")
#define MBAR_EXPECT_TX(addr, bytes) \
    asm volatile("mbarrier.arrive.expect_tx.shared.b64 _, [%0], %1;" :: "r"(addr), "r"(bytes) : "memory")

__device__ __forceinline__ void mbar_wait(uint32_t mbar, uint32_t parity) {
    uint32_t done;
    asm volatile(
        "{\n\t.reg .pred p;\n\t"
        "mbarrier.try_wait.parity.acquire.cta.shared::cta.b64 p, [%1], %2;\n\t"
        "selp.b32 %0, 1, 0, p;\n\t}"
        : "=r"(done) : "r"(mbar), "r"(parity) : "memory");
    if (!done) {
        asm volatile(
            "{\n\t.reg .pred P1;\n\t"
            "W_%=:\n\t"
            "mbarrier.try_wait.parity.acquire.cta.shared::cta.b64 P1, [%0], %1, 0x989680;\n\t"
            "@P1 bra.uni D_%=;\n\t"
            "bra.uni W_%=;\n\t"
            "D_%=:\n\t}"
            :: "r"(mbar), "r"(parity) : "memory");
    }
}

#define TMA_LOAD_2D(dst, tmap, cx, cy, mbar) \
    asm volatile("cp.async.bulk.tensor.2d.shared::cluster.global.tile.mbarrier::complete_tx::bytes " \
                 "[%0], [%1, {%2, %3}], [%4];" \
                 :: "r"(dst), "l"(tmap), "r"(cx), "r"(cy), "r"(mbar) : "memory")

#define LDSM_X4(r, addr) \
    asm volatile("ldmatrix.sync.aligned.m8n8.x4.shared.b16 {%0,%1,%2,%3}, [%4];" \
                 : "=r"((r)[0]), "=r"((r)[1]), "=r"((r)[2]), "=r"((r)[3]) : "r"(addr))

#define MMA_F16(c, a, b0, b1) \
    asm volatile("mma.sync.aligned.m16n8k16.row.col.f32.f16.f16.f32 " \
                 "{%0,%1,%2,%3}, {%4,%5,%6,%7}, {%8,%9}, {%0,%1,%2,%3};" \
                 : "+f"((c)[0]), "+f"((c)[1]), "+f"((c)[2]), "+f"((c)[3]) \
                 : "r"((a)[0]), "r"((a)[1]), "r"((a)[2]), "r"((a)[3]), "r"(b0), "r"(b1))

// ---------------------------------------------------------------------------
// Conversion: fp32 -> fp16, x and B merged into one launch.
// ---------------------------------------------------------------------------
#define NXB ((T_DIM * D_DIM / 4) / 256)   // 8192
#define NBB ((H_DIM * D_DIM / 4) / 256)   // 2048

__global__ __launch_bounds__(256)
void convert_kernel(const float* __restrict__ x, const float* __restrict__ Bm) {
    int b = blockIdx.x;
    const float* src;
    __half* dst;
    size_t i4;
    if (b < NXB) {
        src = x;  dst = g_Axh;
        i4 = (size_t)b * 256 + threadIdx.x;
    } else {
        src = Bm; dst = g_Bh;
        i4 = (size_t)(b - NXB) * 256 + threadIdx.x;
    }
    size_t base = i4 * 4;
    float4 v = *reinterpret_cast<const float4*>(&src[base]);
    __half2 a = __halves2half2(__float2half_rn(v.x), __float2half_rn(v.y));
    __half2 c = __halves2half2(__float2half_rn(v.z), __float2half_rn(v.w));
    __half2* p = reinterpret_cast<__half2*>(&dst[base]);
    p[0] = a; p[1] = c;
}

// ---------------------------------------------------------------------------
// fp16 mma.sync GEMM: u = x_f16 * B_f16  (fp32 accumulate)
// Block tile 128x128, 256 threads (2x4 warps), warp tile 64x32.
// 3-stage TMA pipeline, 2 CTAs/SM. All LDSM of a k16 step hoisted ahead of
// its 16 MMAs. Epilogue fuses TWO 64-row half-chunk carries per tile.
// ---------------------------------------------------------------------------
#define BM 128
#define BN 128
#define A_SUB 16384
#define B_SUB 16384
#define STAGE_BYTES (A_SUB + B_SUB)        // 32 KB
#define NPIPE 3
#define SMEM_BUFS 1024
#define SMEM_TOTAL (SMEM_BUFS + NPIPE * STAGE_BYTES)  // 99328
#define KSTAGES (D_DIM / 64)               // 16
#define CPAD 132

__global__ __launch_bounds__(256, 2)
void gemm_mma_kernel(const __grid_constant__ CUtensorMap tma_a,
                     const __grid_constant__ CUtensorMap tma_b,
                     const float* __restrict__ lamda) {
    extern __shared__ __align__(1024) char smem[];
    const uint32_t sb = smem_u32(smem);
    const int tid = threadIdx.x;
    const int wid = tid >> 5, lane = tid & 31;
    const int warp_m = wid >> 2;          // 0..1  (64 t-rows each)
    const int warp_n = wid & 3;           // 0..3  (32 h-cols each)

    const int h0 = blockIdx.x * BN;
    const int t0 = blockIdx.y * BM;

    if (tid == 0) {
#pragma unroll
        for (int i = 0; i < NPIPE; ++i) MBAR_INIT(sb + i * 8, 1);
    }
    __syncthreads();

    auto issue_stage = [&](int s) {
        const int slot = s % NPIPE;
        const uint32_t mbar = sb + slot * 8;
        const uint32_t buf = sb + SMEM_BUFS + slot * STAGE_BYTES;
        MBAR_EXPECT_TX(mbar, STAGE_BYTES);
        TMA_LOAD_2D(buf,         &tma_a, s * 128, t0, mbar);
        TMA_LOAD_2D(buf + A_SUB, &tma_b, s * 128, h0, mbar);
    };

    float acc[4][4][4];
#pragma unroll
    for (int i = 0; i < 4; ++i)
#pragma unroll
        for (int j = 0; j < 4; ++j)
#pragma unroll
            for (int q = 0; q < 4; ++q) acc[i][j][q] = 0.0f;

    if (tid == 0) { issue_stage(0); issue_stage(1); issue_stage(2); }

    for (int s = 0; s < KSTAGES; ++s) {
        mbar_wait(sb + (s % NPIPE) * 8, (uint32_t)((s / NPIPE) & 1));

        const uint32_t ab = sb + SMEM_BUFS + (s % NPIPE) * STAGE_BYTES;
        const uint32_t bb = ab + A_SUB;
        const uint32_t co = (uint32_t)(lane >> 4) * 16;

#pragma unroll
        for (int g = 0; g < 4; ++g) {            // four k16 steps per stage
            const uint32_t kbase = g * 32;

            uint32_t b_f[2][4], a_f[4][4];
#pragma unroll
            for (int bt = 0; bt < 2; ++bt) {
                int row = warp_n * 32 + bt * 16 + (lane & 15);
                LDSM_X4(b_f[bt], bb + swz128((uint32_t)(row * 128) + kbase + co));
            }
#pragma unroll
            for (int mt = 0; mt < 4; ++mt) {
                int row = warp_m * 64 + mt * 16 + (lane & 15);
                LDSM_X4(a_f[mt], ab + swz128((uint32_t)(row * 128) + kbase + co));
            }
#pragma unroll
            for (int mt = 0; mt < 4; ++mt)
#pragma unroll
                for (int nt = 0; nt < 4; ++nt) {
                    const int bt = nt >> 1, hp = nt & 1;
                    MMA_F16(acc[mt][nt], a_f[mt], b_f[bt][hp], b_f[bt][2 + hp]);
                }
        }

        __syncthreads();
        if (tid == 0 && s + 3 < KSTAGES) issue_stage(s + 3);
    }

    // ------ Epilogue: write g_u + fused TWO half-chunk carries per tile ------
    const int r = lane >> 2, c = (lane & 3) * 2;
    float* Cb = g_u + (size_t)(t0 + warp_m * 64) * H_DIM + h0 + warp_n * 32;
    float* sf = reinterpret_cast<float*>(smem + SMEM_BUFS);   // [128][CPAD] staging

#pragma unroll
    for (int mt = 0; mt < 4; ++mt) {
#pragma unroll
        for (int nt = 0; nt < 4; ++nt) {
            float2 v0 = make_float2(acc[mt][nt][0], acc[mt][nt][1]);
            float2 v1 = make_float2(acc[mt][nt][2], acc[mt][nt][3]);
            const int tl0 = warp_m * 64 + mt * 16 + r;
            const int hl  = warp_n * 32 + nt * 8 + c;
            *reinterpret_cast<float2*>(&Cb[(size_t)(mt * 16 + r) * H_DIM + nt * 8 + c]) = v0;
            *reinterpret_cast<float2*>(&Cb[(size_t)(mt * 16 + r + 8) * H_DIM + nt * 8 + c]) = v1;
            *reinterpret_cast<float2*>(&sf[tl0 * CPAD + hl]) = v0;
            *reinterpret_cast<float2*>(&sf[(tl0 + 8) * CPAD + hl]) = v1;
        }
    }
    __syncthreads();

    if (tid < BN) {
        const float a = 1.0f / (1.0f + expf(-lamda[h0 + tid]));
        float sc = 0.0f;
#pragma unroll 8
        for (int t = 0; t < CHUNK2; ++t) sc = fmaf(a, sc, sf[t * CPAD + tid]);
        g_carry[(2 * blockIdx.y) * H_DIM + h0 + tid] = sc;
        sc = 0.0f;
#pragma unroll 8
        for (int t = CHUNK2; t < 2 * CHUNK2; ++t) sc = fmaf(a, sc, sf[t * CPAD + tid]);
        g_carry[(2 * blockIdx.y + 1) * H_DIM + h0 + tid] = sc;
    }
}

// ---------------------------------------------------------------------------
// Scan pass 2: combine 128 half-chunk carries; full 128-reg prefetch (MLP),
// then the sequential register chain. (Flat prefetch — batched form regressed.)
// ---------------------------------------------------------------------------
__global__ __launch_bounds__(256)
void combine_kernel(const float* __restrict__ lamda) {
    const int h = blockIdx.x * blockDim.x + threadIdx.x;
    const float a = 1.0f / (1.0f + expf(-lamda[h]));
    float aC = a;
#pragma unroll
    for (int i = 0; i < 6; ++i) aC *= aC;  // a^64

    float car[NC2];
#pragma unroll
    for (int c = 0; c < NC2; ++c) car[c] = g_carry[c * H_DIM + h];

    float state = 0.0f;
#pragma unroll
    for (int c = 0; c < NC2; ++c) {
        g_init[c * H_DIM + h] = state;
        state = fmaf(aC, state, car[c]);
    }
}

// ---------------------------------------------------------------------------
// Scan pass 3: 64-step half-chunks, 512 CTAs (grid (4,128)) for latency hiding.
// ---------------------------------------------------------------------------
__global__ __launch_bounds__(128)
void apply_kernel(const float* __restrict__ lamda, float* __restrict__ out) {
    const int h4 = (blockIdx.x * blockDim.x + threadIdx.x) * 4;
    const int c = blockIdx.y;
    float4 lam = *reinterpret_cast<const float4*>(&lamda[h4]);
    float4 a;
    a.x = 1.0f / (1.0f + expf(-lam.x));
    a.y = 1.0f / (1.0f + expf(-lam.y));
    a.z = 1.0f / (1.0f + expf(-lam.z));
    a.w = 1.0f / (1.0f + expf(-lam.w));
    float4 s = *reinterpret_cast<const float4*>(&g_init[c * H_DIM + h4]);
    const size_t base = (size_t)c * CHUNK2 * H_DIM + h4;
#pragma unroll 4
    for (int t = 0; t < CHUNK2; ++t) {
        float4 u = *reinterpret_cast<const float4*>(&g_u[base + (size_t)t * H_DIM]);
        s.x = fmaf(a.x, s.x, u.x);
        s.y = fmaf(a.y, s.y, u.y);
        s.z = fmaf(a.z, s.z, u.z);
        s.w = fmaf(a.w, s.w, u.w);
        *reinterpret_cast<float4*>(&out[base + (size_t)t * H_DIM]) = s;
    }
}

// ---------------------------------------------------------------------------
// Host: TMA descriptor creation via runtime entry point
// ---------------------------------------------------------------------------
typedef CUresult (*PFN_tmapEncode)(
    CUtensorMap*, CUtensorMapDataType, cuuint32_t, void*,
    const cuuint64_t*, const cuuint64_t*, const cuuint32_t*, const cuuint32_t*,
    CUtensorMapInterleave, CUtensorMapSwizzle, CUtensorMapL2promotion,
    CUtensorMapFloatOOBfill);

extern "C" void kernel_launch(void* const* d_in, const int* in_sizes, int n_in,
                              void* d_out, int out_size) {
    const float* x     = (const float*)d_in[0];  // [T, D]
    const float* lamda = (const float*)d_in[1];  // [H]
    const float* Bm    = (const float*)d_in[2];  // [H, D]
    float* out = (float*)d_out;                  // [T, H]

    void* pfn = nullptr;
    cudaDriverEntryPointQueryResult qres;
    cudaGetDriverEntryPoint("cuTensorMapEncodeTiled", &pfn, cudaEnableDefault, &qres);
    PFN_tmapEncode encode = (PFN_tmapEncode)pfn;

    void *ax_ptr = nullptr, *bx_ptr = nullptr;
    cudaGetSymbolAddress(&ax_ptr, g_Axh);
    cudaGetSymbolAddress(&bx_ptr, g_Bh);

    CUtensorMap tma_a, tma_b;
    {
        cuuint64_t dims[2]    = {KROW_BYTES, T_DIM};
        cuuint64_t strides[1] = {KROW_BYTES};
        cuuint32_t box[2]     = {128, BM};
        cuuint32_t es[2]      = {1, 1};
        encode(&tma_a, CU_TENSOR_MAP_DATA_TYPE_UINT8, 2, ax_ptr,
               dims, strides, box, es,
               CU_TENSOR_MAP_INTERLEAVE_NONE, CU_TENSOR_MAP_SWIZZLE_128B,
               CU_TENSOR_MAP_L2_PROMOTION_L2_128B, CU_TENSOR_MAP_FLOAT_OOB_FILL_NONE);
    }
    {
        cuuint64_t dims[2]    = {KROW_BYTES, H_DIM};
        cuuint64_t strides[1] = {KROW_BYTES};
        cuuint32_t box[2]     = {128, BN};
        cuuint32_t es[2]      = {1, 1};
        encode(&tma_b, CU_TENSOR_MAP_DATA_TYPE_UINT8, 2, bx_ptr,
               dims, strides, box, es,
               CU_TENSOR_MAP_INTERLEAVE_NONE, CU_TENSOR_MAP_SWIZZLE_128B,
               CU_TENSOR_MAP_L2_PROMOTION_L2_128B, CU_TENSOR_MAP_FLOAT_OOB_FILL_NONE);
    }

    convert_kernel<<<NXB + NBB, 256>>>(x, Bm);

    cudaFuncSetAttribute(gemm_mma_kernel, cudaFuncAttributeMaxDynamicSharedMemorySize, SMEM_TOTAL);
    dim3 ggrid(H_DIM / BN, T_DIM / BM);   // (16, 64)
    gemm_mma_kernel<<<ggrid, 256, SMEM_TOTAL>>>(tma_a, tma_b, lamda);

    combine_kernel<<<H_DIM / 256, 256>>>(lamda);
    dim3 agrid(H_DIM / 4 / 128, NC2);     // (4, 128) = 512 CTAs
    apply_kernel<<<agrid, 128>>>(lamda, out);
}

// round 16
// speedup vs baseline: 1.4750x; 1.0168x over previous
#include <cuda_runtime.h>
#include <cuda.h>
#include <cuda_fp16.h>
#include <math.h>
#include <stdint.h>

// Problem constants
#define T_DIM 8192
#define H_DIM 2048
#define D_DIM 1024

#define KROW_BYTES (D_DIM * 2)        // 2048

// GEMM tile is 128 rows; scan chunk is 32 rows (4 per tile).
#define CHUNK_S 32
#define NCS (T_DIM / CHUNK_S)         // 256

// Scratch (allocation-free: __device__ globals)
__device__ float   g_u[(size_t)T_DIM * H_DIM];        // 64 MB
__device__ __half  g_Axh[(size_t)T_DIM * D_DIM];      // 16 MB
__device__ __half  g_Bh[(size_t)H_DIM * D_DIM];       // 4 MB
__device__ float   g_carry[NCS * H_DIM];
__device__ float   g_init[NCS * H_DIM];

// ---------------------------------------------------------------------------
// helpers
// ---------------------------------------------------------------------------
__device__ __forceinline__ uint32_t smem_u32(const void* p) {
    uint32_t a;
    asm("{ .reg .u64 t; cvta.to.shared.u64 t, %1; cvt.u32.u64 %0, t; }" : "=r"(a) : "l"(p));
    return a;
}
__device__ __forceinline__ uint32_t swz128(uint32_t off) { return off ^ ((off >> 3) & 0x70); }

#define MBAR_INIT(addr, cnt) \
    asm volatile("mbarrier.init.shared.b64 [%0], %1;" :: "r"(addr), "r"(cnt) : "memory")
#define MBAR_EXPECT_TX(addr, bytes) \
    asm volatile("mbarrier.arrive.expect_tx.shared.b64 _, [%0], %1;" :: "r"(addr), "r"(bytes) : "memory")

__device__ __forceinline__ void mbar_wait(uint32_t mbar, uint32_t parity) {
    uint32_t done;
    asm volatile(
        "{\n\t.reg .pred p;\n\t"
        "mbarrier.try_wait.parity.acquire.cta.shared::cta.b64 p, [%1], %2;\n\t"
        "selp.b32 %0, 1, 0, p;\n\t}"
        : "=r"(done) : "r"(mbar), "r"(parity) : "memory");
    if (!done) {
        asm volatile(
            "{\n\t.reg .pred P1;\n\t"
            "W_%=:\n\t"
            "mbarrier.try_wait.parity.acquire.cta.shared::cta.b64 P1, [%0], %1, 0x989680;\n\t"
            "@P1 bra.uni D_%=;\n\t"
            "bra.uni W_%=;\n\t"
            "D_%=:\n\t}"
            :: "r"(mbar), "r"(parity) : "memory");
    }
}

#define TMA_LOAD_2D(dst, tmap, cx, cy, mbar) \
    asm volatile("cp.async.bulk.tensor.2d.shared::cluster.global.tile.mbarrier::complete_tx::bytes " \
                 "[%0], [%1, {%2, %3}], [%4];" \
                 :: "r"(dst), "l"(tmap), "r"(cx), "r"(cy), "r"(mbar) : "memory")

#define LDSM_X4(r, addr) \
    asm volatile("ldmatrix.sync.aligned.m8n8.x4.shared.b16 {%0,%1,%2,%3}, [%4];" \
                 : "=r"((r)[0]), "=r"((r)[1]), "=r"((r)[2]), "=r"((r)[3]) : "r"(addr))

#define MMA_F16(c, a, b0, b1) \
    asm volatile("mma.sync.aligned.m16n8k16.row.col.f32.f16.f16.f32 " \
                 "{%0,%1,%2,%3}, {%4,%5,%6,%7}, {%8,%9}, {%0,%1,%2,%3};" \
                 : "+f"((c)[0]), "+f"((c)[1]), "+f"((c)[2]), "+f"((c)[3]) \
                 : "r"((a)[0]), "r"((a)[1]), "r"((a)[2]), "r"((a)[3]), "r"(b0), "r"(b1))

// ---------------------------------------------------------------------------
// Conversion: fp32 -> fp16, x and B merged into one launch.
// ---------------------------------------------------------------------------
#define NXB ((T_DIM * D_DIM / 4) / 256)   // 8192
#define NBB ((H_DIM * D_DIM / 4) / 256)   // 2048

__global__ __launch_bounds__(256)
void convert_kernel(const float* __restrict__ x, const float* __restrict__ Bm) {
    int b = blockIdx.x;
    const float* src;
    __half* dst;
    size_t i4;
    if (b < NXB) {
        src = x;  dst = g_Axh;
        i4 = (size_t)b * 256 + threadIdx.x;
    } else {
        src = Bm; dst = g_Bh;
        i4 = (size_t)(b - NXB) * 256 + threadIdx.x;
    }
    size_t base = i4 * 4;
    float4 v = *reinterpret_cast<const float4*>(&src[base]);
    __half2 a = __halves2half2(__float2half_rn(v.x), __float2half_rn(v.y));
    __half2 c = __halves2half2(__float2half_rn(v.z), __float2half_rn(v.w));
    __half2* p = reinterpret_cast<__half2*>(&dst[base]);
    p[0] = a; p[1] = c;
}

// ---------------------------------------------------------------------------
// fp16 mma.sync GEMM: u = x_f16 * B_f16  (fp32 accumulate)
// Block tile 128x128, 256 threads (2x4 warps), warp tile 64x32.
// 3-stage TMA pipeline, 2 CTAs/SM. All LDSM of a k16 step hoisted ahead of
// its 16 MMAs. Epilogue fuses FOUR 32-row quarter-chunk carries per tile.
// ---------------------------------------------------------------------------
#define BM 128
#define BN 128
#define A_SUB 16384
#define B_SUB 16384
#define STAGE_BYTES (A_SUB + B_SUB)        // 32 KB
#define NPIPE 3
#define SMEM_BUFS 1024
#define SMEM_TOTAL (SMEM_BUFS + NPIPE * STAGE_BYTES)  // 99328
#define KSTAGES (D_DIM / 64)               // 16
#define CPAD 132

__global__ __launch_bounds__(256, 2)
void gemm_mma_kernel(const __grid_constant__ CUtensorMap tma_a,
                     const __grid_constant__ CUtensorMap tma_b,
                     const float* __restrict__ lamda) {
    extern __shared__ __align__(1024) char smem[];
    const uint32_t sb = smem_u32(smem);
    const int tid = threadIdx.x;
    const int wid = tid >> 5, lane = tid & 31;
    const int warp_m = wid >> 2;          // 0..1  (64 t-rows each)
    const int warp_n = wid & 3;           // 0..3  (32 h-cols each)

    const int h0 = blockIdx.x * BN;
    const int t0 = blockIdx.y * BM;

    if (tid == 0) {
#pragma unroll
        for (int i = 0; i < NPIPE; ++i) MBAR_INIT(sb + i * 8, 1);
    }
    __syncthreads();

    auto issue_stage = [&](int s) {
        const int slot = s % NPIPE;
        const uint32_t mbar = sb + slot * 8;
        const uint32_t buf = sb + SMEM_BUFS + slot * STAGE_BYTES;
        MBAR_EXPECT_TX(mbar, STAGE_BYTES);
        TMA_LOAD_2D(buf,         &tma_a, s * 128, t0, mbar);
        TMA_LOAD_2D(buf + A_SUB, &tma_b, s * 128, h0, mbar);
    };

    float acc[4][4][4];
#pragma unroll
    for (int i = 0; i < 4; ++i)
#pragma unroll
        for (int j = 0; j < 4; ++j)
#pragma unroll
            for (int q = 0; q < 4; ++q) acc[i][j][q] = 0.0f;

    if (tid == 0) { issue_stage(0); issue_stage(1); issue_stage(2); }

    for (int s = 0; s < KSTAGES; ++s) {
        mbar_wait(sb + (s % NPIPE) * 8, (uint32_t)((s / NPIPE) & 1));

        const uint32_t ab = sb + SMEM_BUFS + (s % NPIPE) * STAGE_BYTES;
        const uint32_t bb = ab + A_SUB;
        const uint32_t co = (uint32_t)(lane >> 4) * 16;

#pragma unroll
        for (int g = 0; g < 4; ++g) {            // four k16 steps per stage
            const uint32_t kbase = g * 32;

            uint32_t b_f[2][4], a_f[4][4];
#pragma unroll
            for (int bt = 0; bt < 2; ++bt) {
                int row = warp_n * 32 + bt * 16 + (lane & 15);
                LDSM_X4(b_f[bt], bb + swz128((uint32_t)(row * 128) + kbase + co));
            }
#pragma unroll
            for (int mt = 0; mt < 4; ++mt) {
                int row = warp_m * 64 + mt * 16 + (lane & 15);
                LDSM_X4(a_f[mt], ab + swz128((uint32_t)(row * 128) + kbase + co));
            }
#pragma unroll
            for (int mt = 0; mt < 4; ++mt)
#pragma unroll
                for (int nt = 0; nt < 4; ++nt) {
                    const int bt = nt >> 1, hp = nt & 1;
                    MMA_F16(acc[mt][nt], a_f[mt], b_f[bt][hp], b_f[bt][2 + hp]);
                }
        }

        __syncthreads();
        if (tid == 0 && s + 3 < KSTAGES) issue_stage(s + 3);
    }

    // ------ Epilogue: write g_u + fused FOUR quarter-chunk carries ----------
    const int r = lane >> 2, c = (lane & 3) * 2;
    float* Cb = g_u + (size_t)(t0 + warp_m * 64) * H_DIM + h0 + warp_n * 32;
    float* sf = reinterpret_cast<float*>(smem + SMEM_BUFS);   // [128][CPAD] staging

#pragma unroll
    for (int mt = 0; mt < 4; ++mt) {
#pragma unroll
        for (int nt = 0; nt < 4; ++nt) {
            float2 v0 = make_float2(acc[mt][nt][0], acc[mt][nt][1]);
            float2 v1 = make_float2(acc[mt][nt][2], acc[mt][nt][3]);
            const int tl0 = warp_m * 64 + mt * 16 + r;
            const int hl  = warp_n * 32 + nt * 8 + c;
            *reinterpret_cast<float2*>(&Cb[(size_t)(mt * 16 + r) * H_DIM + nt * 8 + c]) = v0;
            *reinterpret_cast<float2*>(&Cb[(size_t)(mt * 16 + r + 8) * H_DIM + nt * 8 + c]) = v1;
            *reinterpret_cast<float2*>(&sf[tl0 * CPAD + hl]) = v0;
            *reinterpret_cast<float2*>(&sf[(tl0 + 8) * CPAD + hl]) = v1;
        }
    }
    __syncthreads();

    if (tid < BN) {
        const float a = 1.0f / (1.0f + expf(-lamda[h0 + tid]));
#pragma unroll
        for (int q = 0; q < 4; ++q) {
            float sc = 0.0f;
#pragma unroll 8
            for (int t = q * CHUNK_S; t < (q + 1) * CHUNK_S; ++t)
                sc = fmaf(a, sc, sf[t * CPAD + tid]);
            g_carry[(4 * blockIdx.y + q) * H_DIM + h0 + tid] = sc;
        }
    }
}

// ---------------------------------------------------------------------------
// Scan pass 2: combine 256 quarter-chunk carries.
// Two fully-unrolled batches of 128 register-prefetches (MLP-covered).
// ---------------------------------------------------------------------------
__global__ __launch_bounds__(256)
void combine_kernel(const float* __restrict__ lamda) {
    const int h = blockIdx.x * blockDim.x + threadIdx.x;
    const float a = 1.0f / (1.0f + expf(-lamda[h]));
    float aC = a;
#pragma unroll
    for (int i = 0; i < 5; ++i) aC *= aC;  // a^32

    float state = 0.0f;
#pragma unroll
    for (int b = 0; b < 2; ++b) {
        float car[128];
#pragma unroll
        for (int i = 0; i < 128; ++i) car[i] = g_carry[(b * 128 + i) * H_DIM + h];
#pragma unroll
        for (int i = 0; i < 128; ++i) {
            g_init[(b * 128 + i) * H_DIM + h] = state;
            state = fmaf(aC, state, car[i]);
        }
    }
}

// ---------------------------------------------------------------------------
// Scan pass 3: 32-step quarter-chunks, 1024 CTAs (grid (4,256)).
// ---------------------------------------------------------------------------
__global__ __launch_bounds__(128)
void apply_kernel(const float* __restrict__ lamda, float* __restrict__ out) {
    const int h4 = (blockIdx.x * blockDim.x + threadIdx.x) * 4;
    const int c = blockIdx.y;
    float4 lam = *reinterpret_cast<const float4*>(&lamda[h4]);
    float4 a;
    a.x = 1.0f / (1.0f + expf(-lam.x));
    a.y = 1.0f / (1.0f + expf(-lam.y));
    a.z = 1.0f / (1.0f + expf(-lam.z));
    a.w = 1.0f / (1.0f + expf(-lam.w));
    float4 s = *reinterpret_cast<const float4*>(&g_init[c * H_DIM + h4]);
    const size_t base = (size_t)c * CHUNK_S * H_DIM + h4;
#pragma unroll 4
    for (int t = 0; t < CHUNK_S; ++t) {
        float4 u = *reinterpret_cast<const float4*>(&g_u[base + (size_t)t * H_DIM]);
        s.x = fmaf(a.x, s.x, u.x);
        s.y = fmaf(a.y, s.y, u.y);
        s.z = fmaf(a.z, s.z, u.z);
        s.w = fmaf(a.w, s.w, u.w);
        *reinterpret_cast<float4*>(&out[base + (size_t)t * H_DIM]) = s;
    }
}

// ---------------------------------------------------------------------------
// Host: TMA descriptor creation via runtime entry point
// ---------------------------------------------------------------------------
typedef CUresult (*PFN_tmapEncode)(
    CUtensorMap*, CUtensorMapDataType, cuuint32_t, void*,
    const cuuint64_t*, const cuuint64_t*, const cuuint32_t*, const cuuint32_t*,
    CUtensorMapInterleave, CUtensorMapSwizzle, CUtensorMapL2promotion,
    CUtensorMapFloatOOBfill);

extern "C" void kernel_launch(void* const* d_in, const int* in_sizes, int n_in,
                              void* d_out, int out_size) {
    const float* x     = (const float*)d_in[0];  // [T, D]
    const float* lamda = (const float*)d_in[1];  // [H]
    const float* Bm    = (const float*)d_in[2];  // [H, D]
    float* out = (float*)d_out;                  // [T, H]

    void* pfn = nullptr;
    cudaDriverEntryPointQueryResult qres;
    cudaGetDriverEntryPoint("cuTensorMapEncodeTiled", &pfn, cudaEnableDefault, &qres);
    PFN_tmapEncode encode = (PFN_tmapEncode)pfn;

    void *ax_ptr = nullptr, *bx_ptr = nullptr;
    cudaGetSymbolAddress(&ax_ptr, g_Axh);
    cudaGetSymbolAddress(&bx_ptr, g_Bh);

    CUtensorMap tma_a, tma_b;
    {
        cuuint64_t dims[2]    = {KROW_BYTES, T_DIM};
        cuuint64_t strides[1] = {KROW_BYTES};
        cuuint32_t box[2]     = {128, BM};
        cuuint32_t es[2]      = {1, 1};
        encode(&tma_a, CU_TENSOR_MAP_DATA_TYPE_UINT8, 2, ax_ptr,
               dims, strides, box, es,
               CU_TENSOR_MAP_INTERLEAVE_NONE, CU_TENSOR_MAP_SWIZZLE_128B,
               CU_TENSOR_MAP_L2_PROMOTION_L2_128B, CU_TENSOR_MAP_FLOAT_OOB_FILL_NONE);
    }
    {
        cuuint64_t dims[2]    = {KROW_BYTES, H_DIM};
        cuuint64_t strides[1] = {KROW_BYTES};
        cuuint32_t box[2]     = {128, BN};
        cuuint32_t es[2]      = {1, 1};
        encode(&tma_b, CU_TENSOR_MAP_DATA_TYPE_UINT8, 2, bx_ptr,
               dims, strides, box, es,
               CU_TENSOR_MAP_INTERLEAVE_NONE, CU_TENSOR_MAP_SWIZZLE_128B,
               CU_TENSOR_MAP_L2_PROMOTION_L2_128B, CU_TENSOR_MAP_FLOAT_OOB_FILL_NONE);
    }

    convert_kernel<<<NXB + NBB, 256>>>(x, Bm);

    cudaFuncSetAttribute(gemm_mma_kernel, cudaFuncAttributeMaxDynamicSharedMemorySize, SMEM_TOTAL);
    dim3 ggrid(H_DIM / BN, T_DIM / BM);   // (16, 64)
    gemm_mma_kernel<<<ggrid, 256, SMEM_TOTAL>>>(tma_a, tma_b, lamda);

    combine_kernel<<<H_DIM / 256, 256>>>(lamda);
    dim3 agrid(H_DIM / 4 / 128, NCS);     // (4, 256) = 1024 CTAs
    apply_kernel<<<agrid, 128>>>(lamda, out);
}